// round 15
// baseline (speedup 1.0000x reference)
#include <cuda_runtime.h>
#include <cuda_bf16.h>
#include <cstdint>

#define Nn 50000
#define Ee 800000
#define Dd 64
#define Ll 3
#define Gg 512
#define Ss 32
#define POOLW (2*Dd*Ll)   // 384
#define ZPAD 68           // sZ row stride in floats (17 float4s, 16B aligned)
#define CAP 64            // ELL row capacity (deg ~ Poisson(16); P(>=64) ~ 2e-18)
#define FO (Ee/8)         // 100000 edges per fill-octet

// Scratch (no allocations allowed)
__device__ float g_h[Nn * Dd];
__device__ float g_h2[Nn * Dd];
__device__ float g_agg[Nn * Dd];
__device__ float g_pool[Gg * POOLW];
__device__ int   g_cnt[Nn];
__device__ int2  g_ell[(size_t)Nn * CAP];   // {src*16, __float_as_int(w)} per dst row

// ---------------------------------------------------------------------------
// ELL build: 8 edges per thread, front-batched loads -> 8 independent
// load->atomic->store chains in flight. Stores src PREMULTIPLIED by 16
// (float4-row offset). Scattered stores use .cg (no L1 allocation: the data
// is consumed by a later kernel, after the per-launch L1 flush).
// cnt must be zeroed first.
// ---------------------------------------------------------------------------
__global__ __launch_bounds__(256) void ell_fill_kernel(
    const int* __restrict__ src, const int* __restrict__ dst,
    const float* __restrict__ ew, int* __restrict__ cnt,
    int2* __restrict__ ell)
{
    unsigned e0 = blockIdx.x * 256u + threadIdx.x;
    if (e0 >= FO) return;
    int d[8], s[8]; float w[8];
#pragma unroll
    for (int q = 0; q < 8; q++) {
        unsigned e = e0 + q * (unsigned)FO;
        d[q] = __ldg(dst + e);
        s[q] = __ldg(src + e);
        w[q] = __ldg(ew + e);
    }
    int p[8];
#pragma unroll
    for (int q = 0; q < 8; q++)
        p[q] = atomicAdd(&cnt[d[q]], 1);
#pragma unroll
    for (int q = 0; q < 8; q++)
        if (p[q] < CAP) {
            int2* addr = ell + (size_t)d[q] * CAP + p[q];
            asm volatile("st.global.cg.v2.s32 [%0], {%1, %2};"
                         :: "l"(addr), "r"(s[q] * 16), "r"(__float_as_int(w[q]))
                         : "memory");
        }
}

// ---------------------------------------------------------------------------
// ELL gather: agg[node] = (1+eps)*h[node] + sum_{edges} w * h[src]
// 16 threads per node, 4 columns (1 float4) each. 4-edge unroll with
// double-buffered index loads; premultiplied src -> address = base + idx + lane.
// (R13-validated optimum: ~40 regs, 58% occ; deeper unrolls regress.)
// ---------------------------------------------------------------------------
__global__ __launch_bounds__(256) void gather_kernel(
    const float4* __restrict__ h4,
    const int* __restrict__ cnt,
    const int2* __restrict__ ell, const float* __restrict__ eps_p,
    float4* __restrict__ agg4)
{
    unsigned t = blockIdx.x * 256u + threadIdx.x;
    unsigned node = t >> 4;
    if (node >= Nn) return;
    const int lane = t & 15;         // column quad: cols [lane*4, lane*4+4)
    const float epsv = 1.0f + __ldg(eps_p);

    float4 a0 = h4[(size_t)node * 16 + lane];
    a0.x *= epsv; a0.y *= epsv; a0.z *= epsv; a0.w *= epsv;

    const float4* hl = h4 + lane;    // lane-offset base; edge addr = hl + idx16

    int num = __ldg(cnt + node);
    if (num > CAP) num = CAP;
    const int2* sw = ell + (size_t)node * CAP;
    int j = 0;
    if (num >= 4) {
        int4 pA = __ldg((const int4*)(sw));
        int4 pB = __ldg((const int4*)(sw + 2));
        for (;;) {
            const int jn = j + 4;
            const bool more = (jn + 4 <= num);
            int4 nA, nB;
            if (more) {
                nA = __ldg((const int4*)(sw + jn));
                nB = __ldg((const int4*)(sw + jn + 2));
            }
            float4 v0 = hl[pA.x];
            float4 v1 = hl[pA.z];
            float4 v2 = hl[pB.x];
            float4 v3 = hl[pB.z];
            float w0 = __int_as_float(pA.y), w1 = __int_as_float(pA.w);
            float w2 = __int_as_float(pB.y), w3 = __int_as_float(pB.w);
            a0.x = fmaf(w0, v0.x, a0.x); a0.y = fmaf(w0, v0.y, a0.y);
            a0.z = fmaf(w0, v0.z, a0.z); a0.w = fmaf(w0, v0.w, a0.w);
            a0.x = fmaf(w1, v1.x, a0.x); a0.y = fmaf(w1, v1.y, a0.y);
            a0.z = fmaf(w1, v1.z, a0.z); a0.w = fmaf(w1, v1.w, a0.w);
            a0.x = fmaf(w2, v2.x, a0.x); a0.y = fmaf(w2, v2.y, a0.y);
            a0.z = fmaf(w2, v2.z, a0.z); a0.w = fmaf(w2, v2.w, a0.w);
            a0.x = fmaf(w3, v3.x, a0.x); a0.y = fmaf(w3, v3.y, a0.y);
            a0.z = fmaf(w3, v3.z, a0.z); a0.w = fmaf(w3, v3.w, a0.w);
            j = jn;
            if (!more) break;
            pA = nA; pB = nB;
        }
    }
    for (; j + 2 <= num; j += 2) {
        int4 pA = __ldg((const int4*)(sw + j));
        float4 v0 = hl[pA.x];
        float4 v1 = hl[pA.z];
        float w0 = __int_as_float(pA.y), w1 = __int_as_float(pA.w);
        a0.x = fmaf(w0, v0.x, a0.x); a0.y = fmaf(w0, v0.y, a0.y);
        a0.z = fmaf(w0, v0.z, a0.z); a0.w = fmaf(w0, v0.w, a0.w);
        a0.x = fmaf(w1, v1.x, a0.x); a0.y = fmaf(w1, v1.y, a0.y);
        a0.z = fmaf(w1, v1.z, a0.z); a0.w = fmaf(w1, v1.w, a0.w);
    }
    if (j < num) {
        int2 e0 = __ldg(sw + j);
        float4 v0 = hl[e0.x];
        float w0 = __int_as_float(e0.y);
        a0.x = fmaf(w0, v0.x, a0.x); a0.y = fmaf(w0, v0.y, a0.y);
        a0.z = fmaf(w0, v0.z, a0.z); a0.w = fmaf(w0, v0.w, a0.w);
    }
    agg4[(size_t)node * 16 + lane] = a0;
}

// ---------------------------------------------------------------------------
// Fused per-layer MLP (z already in 'zin'):
//   t = relu(BN(z@W1 + b1)) ; h' = relu(t@W2 + b2)
//   h_out <- h' (direct STG.128) ; pool[batch[r], layer*128+c] += h'*mask[r]
// Single shared weight buffer (W1 then W2). smem ~34.8KB, launch_bounds(256,5)
// -> 5 CTAs/SM (R11-validated optimum; 6 causes register spills).
// Blocks < 32 also write the previous layer's center rows.
// ---------------------------------------------------------------------------
__global__ __launch_bounds__(256, 5) void fused_mlp(
    const float* __restrict__ zin, const float* __restrict__ h_prev,
    const float* __restrict__ W1, const float* __restrict__ b1,
    const float* __restrict__ gamma, const float* __restrict__ beta,
    const float* __restrict__ bn_mean, const float* __restrict__ bn_var,
    const float* __restrict__ W2, const float* __restrict__ b2,
    float* __restrict__ h_out, const float* __restrict__ mask,
    const int* __restrict__ batch, const int* __restrict__ mapping,
    float* __restrict__ pool, int layer)
{
    extern __shared__ float sm[];
    float* sW = sm;                    // 4096 floats (64x64), W1 then W2
    float* sZ = sm + 4096;             // 64 x ZPAD (z, then t in-place)
    __shared__ float sScale[64], sShift[64], sB1[64], sB2[64];

    const int tid = threadIdx.x;
    const int rowBase = blockIdx.x * 64;

    float4* sWv = (float4*)sW;
    const float4* W1v = (const float4*)W1;
    const float4* W2v = (const float4*)W2;
#pragma unroll
    for (int i = 0; i < 4; i++)
        sWv[tid + i * 256] = W1v[tid + i * 256];
    if (tid < 64) {
        float sc = __ldg(gamma + tid) * rsqrtf(__ldg(bn_var + tid) + 1e-5f);
        sScale[tid] = sc;
        sShift[tid] = __ldg(beta + tid) - __ldg(bn_mean + tid) * sc;
        sB1[tid] = __ldg(b1 + tid);
        sB2[tid] = __ldg(b2 + tid);
    }

    // Previous layer's center gather (h_prev is the completed previous output)
    if (layer > 0 && blockIdx.x < 32) {
        int t2 = blockIdx.x * 256 + tid;   // 0..8191 = 512*16
        int gg = t2 >> 4, cc = t2 & 15;
        ((float4*)pool)[gg * (POOLW / 4) + (layer - 1) * 32 + 16 + cc] =
            ((const float4*)h_prev)[(size_t)__ldg(mapping + gg) * 16 + cc];
    }

    // Load z tile (row-major, stride ZPAD)
    const float4* z4 = (const float4*)zin;
#pragma unroll
    for (int i = 0; i < 4; i++) {
        int t = tid + i * 256;
        int r = t >> 4, c4 = t & 15;
        int gr = rowBase + r;
        float4 z = (gr < Nn) ? z4[(size_t)gr * 16 + c4]
                             : make_float4(0.f, 0.f, 0.f, 0.f);
        *(float4*)&sZ[r * ZPAD + c4 * 4] = z;
    }
    __syncthreads();

    const int tx = tid & 15, ty = tid >> 4;
    const int c0 = tx * 4, r0 = ty * 4;

    // ---- GEMM1: acc = z @ W1 (FFMA2; A via LDS.128 per 4k, B per-kk LDS.128)
    unsigned long long acc01[4] = {}, acc23[4] = {};
    {
        const float4* sZr = (const float4*)sZ;
        const ulonglong2* sWq = (const ulonglong2*)sW;
#pragma unroll
        for (int k4 = 0; k4 < 16; k4++) {
            float4 av[4];
#pragma unroll
            for (int i = 0; i < 4; i++)
                av[i] = sZr[(r0 + i) * (ZPAD / 4) + k4];
#pragma unroll
            for (int kk = 0; kk < 4; kk++) {
                ulonglong2 b = sWq[(k4 * 4 + kk) * 16 + tx];
#pragma unroll
                for (int i = 0; i < 4; i++) {
                    float a = (kk == 0) ? av[i].x : (kk == 1) ? av[i].y
                            : (kk == 2) ? av[i].z : av[i].w;
                    unsigned au = __float_as_uint(a);
                    unsigned long long aa;
                    asm("mov.b64 %0, {%1, %1};" : "=l"(aa) : "r"(au));
                    asm("fma.rn.f32x2 %0, %1, %2, %0;" : "+l"(acc01[i]) : "l"(aa), "l"(b.x));
                    asm("fma.rn.f32x2 %0, %1, %2, %0;" : "+l"(acc23[i]) : "l"(aa), "l"(b.y));
                }
            }
        }
    }
    __syncthreads();   // all GEMM1 reads of sZ and sW complete

    // Reload weight buffer with W2 (L2-broadcast-hot across CTAs)
#pragma unroll
    for (int i = 0; i < 4; i++)
        sWv[tid + i * 256] = W2v[tid + i * 256];

    // +b1, BN(eval), ReLU -> back into sZ (t tile, same ZPAD layout)
    {
        float4 bb1 = *(const float4*)&sB1[c0];
        float4 scv = *(const float4*)&sScale[c0];
        float4 shv = *(const float4*)&sShift[c0];
#pragma unroll
        for (int i = 0; i < 4; i++) {
            unsigned u0, u1, u2, u3;
            asm("mov.b64 {%0, %1}, %2;" : "=r"(u0), "=r"(u1) : "l"(acc01[i]));
            asm("mov.b64 {%0, %1}, %2;" : "=r"(u2), "=r"(u3) : "l"(acc23[i]));
            float4 v;
            v.x = fmaxf(fmaf(__uint_as_float(u0) + bb1.x, scv.x, shv.x), 0.f);
            v.y = fmaxf(fmaf(__uint_as_float(u1) + bb1.y, scv.y, shv.y), 0.f);
            v.z = fmaxf(fmaf(__uint_as_float(u2) + bb1.z, scv.z, shv.z), 0.f);
            v.w = fmaxf(fmaf(__uint_as_float(u3) + bb1.w, scv.w, shv.w), 0.f);
            *(float4*)&sZ[(r0 + i) * ZPAD + c0] = v;
        }
    }
    __syncthreads();   // t and W2 visible

    // ---- GEMM2: acc2 = t @ W2
    unsigned long long bcc01[4] = {}, bcc23[4] = {};
    {
        const float4* sTr = (const float4*)sZ;
        const ulonglong2* sWq = (const ulonglong2*)sW;
#pragma unroll
        for (int k4 = 0; k4 < 16; k4++) {
            float4 av[4];
#pragma unroll
            for (int i = 0; i < 4; i++)
                av[i] = sTr[(r0 + i) * (ZPAD / 4) + k4];
#pragma unroll
            for (int kk = 0; kk < 4; kk++) {
                ulonglong2 b = sWq[(k4 * 4 + kk) * 16 + tx];
#pragma unroll
                for (int i = 0; i < 4; i++) {
                    float a = (kk == 0) ? av[i].x : (kk == 1) ? av[i].y
                            : (kk == 2) ? av[i].z : av[i].w;
                    unsigned au = __float_as_uint(a);
                    unsigned long long aa;
                    asm("mov.b64 %0, {%1, %1};" : "=l"(aa) : "r"(au));
                    asm("fma.rn.f32x2 %0, %1, %2, %0;" : "+l"(bcc01[i]) : "l"(aa), "l"(b.x));
                    asm("fma.rn.f32x2 %0, %1, %2, %0;" : "+l"(bcc23[i]) : "l"(aa), "l"(b.y));
                }
            }
        }
    }

    // +b2, ReLU -> DIRECT global write (STG.128, coalesced across tx) + pool red
    {
        float4 bb2 = *(const float4*)&sB2[c0];
        float4* ho4 = (float4*)h_out;
#pragma unroll
        for (int i = 0; i < 4; i++) {
            int gr = rowBase + r0 + i;
            if (gr >= Nn) continue;
            unsigned u0, u1, u2, u3;
            asm("mov.b64 {%0, %1}, %2;" : "=r"(u0), "=r"(u1) : "l"(bcc01[i]));
            asm("mov.b64 {%0, %1}, %2;" : "=r"(u2), "=r"(u3) : "l"(bcc23[i]));
            float4 v;
            v.x = fmaxf(__uint_as_float(u0) + bb2.x, 0.f);
            v.y = fmaxf(__uint_as_float(u1) + bb2.y, 0.f);
            v.z = fmaxf(__uint_as_float(u2) + bb2.z, 0.f);
            v.w = fmaxf(__uint_as_float(u3) + bb2.w, 0.f);
            ho4[(size_t)gr * 16 + tx] = v;
            float w = __ldg(mask + gr);
            if (w != 0.f) {
                float* addr = pool + (size_t)__ldg(batch + gr) * POOLW + layer * 128 + c0;
                float4 p = make_float4(v.x * w, v.y * w, v.z * w, v.w * w);
                asm volatile("red.global.add.v4.f32 [%0], {%1, %2, %3, %4};"
                             :: "l"(addr), "f"(p.x), "f"(p.y), "f"(p.z), "f"(p.w)
                             : "memory");
            }
        }
    }
}

// ---------------------------------------------------------------------------
// Final projection with fused layer-2 center gather:
// out[g,s] = sum_{k<320} pool[g,k]*lw[k,s] + sum_{k<64} h[map[g],k]*lw[320+k,s] + lb[s]
// ---------------------------------------------------------------------------
__global__ __launch_bounds__(128) void final_kernel(
    const float* __restrict__ pool, const float* __restrict__ hfin,
    const int* __restrict__ mapping,
    const float* __restrict__ lw, const float* __restrict__ lb,
    float* __restrict__ out)
{
    int g = blockIdx.x * 4 + (threadIdx.x >> 5);
    int s = threadIdx.x & 31;
    const float* pr = pool + (size_t)g * POOLW;
    const float* hc = hfin + (size_t)__ldg(mapping + g) * Dd;
    float acc = __ldg(lb + s);
#pragma unroll 4
    for (int k = 0; k < 320; k++)
        acc = fmaf(__ldg(pr + k), __ldg(lw + k * Ss + s), acc);
#pragma unroll 4
    for (int k = 0; k < Dd; k++)
        acc = fmaf(__ldg(hc + k), __ldg(lw + (320 + k) * Ss + s), acc);
    out[g * Ss + s] = acc;
}

extern "C" void kernel_launch(void* const* d_in, const int* in_sizes, int n_in,
                              void* d_out, int out_size)
{
    const float* x       = (const float*)d_in[0];
    const float* ew      = (const float*)d_in[1];
    const float* mask    = (const float*)d_in[2];
    const float* W1      = (const float*)d_in[3];
    const float* b1      = (const float*)d_in[4];
    const float* gamma   = (const float*)d_in[5];
    const float* beta    = (const float*)d_in[6];
    const float* bn_mean = (const float*)d_in[7];
    const float* bn_var  = (const float*)d_in[8];
    const float* W2      = (const float*)d_in[9];
    const float* b2      = (const float*)d_in[10];
    const float* eps     = (const float*)d_in[11];
    const float* lin_w   = (const float*)d_in[12];
    const float* lin_b   = (const float*)d_in[13];
    const int* edge_index = (const int*)d_in[14];
    const int* batch      = (const int*)d_in[15];
    const int* mapping    = (const int*)d_in[16];
    float* out = (float*)d_out;

    float *hbuf = nullptr, *hbuf2 = nullptr, *aggbuf = nullptr, *poolbuf = nullptr;
    int *cntb = nullptr;
    int2 *ellb = nullptr;
    (void)cudaGetSymbolAddress((void**)&hbuf, g_h);
    (void)cudaGetSymbolAddress((void**)&hbuf2, g_h2);
    (void)cudaGetSymbolAddress((void**)&aggbuf, g_agg);
    (void)cudaGetSymbolAddress((void**)&poolbuf, g_pool);
    (void)cudaGetSymbolAddress((void**)&cntb, g_cnt);
    (void)cudaGetSymbolAddress((void**)&ellb, g_ell);

    const int SMEM_BYTES = (4096 + 64*ZPAD) * (int)sizeof(float);  // ~33.8KB
    (void)cudaFuncSetAttribute(fused_mlp, cudaFuncAttributeMaxDynamicSharedMemorySize, SMEM_BYTES);

    cudaMemsetAsync(cntb, 0, Nn * sizeof(int));
    cudaMemsetAsync(poolbuf, 0, (size_t)Gg * POOLW * sizeof(float));

    const int* srcp = edge_index;
    const int* dstp = edge_index + Ee;

    ell_fill_kernel<<<(FO + 255) / 256, 256>>>(srcp, dstp, ew, cntb, ellb);

    const float* hin = x;
    float* houts[3] = {hbuf, hbuf2, hbuf};
    for (int l = 0; l < Ll; l++) {
        gather_kernel<<<(Nn * 16 + 255) / 256, 256>>>(
            (const float4*)hin, cntb, ellb, eps + l, (float4*)aggbuf);
        fused_mlp<<<(Nn + 63) / 64, 256, SMEM_BYTES>>>(
            aggbuf, hin,
            W1 + l * Dd * Dd, b1 + l * Dd,
            gamma + l * Dd, beta + l * Dd, bn_mean + l * Dd, bn_var + l * Dd,
            W2 + l * Dd * Dd, b2 + l * Dd,
            houts[l], mask, batch, mapping, poolbuf, l);
        hin = houts[l];
    }
    final_kernel<<<Gg / 4, 128>>>(poolbuf, hbuf, mapping, lin_w, lin_b, out);
}

// round 16
// speedup vs baseline: 1.4427x; 1.4427x over previous
#include <cuda_runtime.h>
#include <cuda_bf16.h>
#include <cstdint>

#define Nn 50000
#define Ee 800000
#define Dd 64
#define Ll 3
#define Gg 512
#define Ss 32
#define POOLW (2*Dd*Ll)   // 384
#define ZPAD 68           // sZ row stride in floats (17 float4s, 16B aligned)
#define CAP 64            // ELL row capacity (deg ~ Poisson(16); P(>=64) ~ 2e-18)
#define FO (Ee/8)         // 100000 edges per fill-octet

// Scratch (no allocations allowed)
__device__ float g_h[Nn * Dd];
__device__ float g_h2[Nn * Dd];
__device__ float g_agg[Nn * Dd];
__device__ float g_pool[Gg * POOLW];
__device__ int   g_cnt[Nn];
__device__ int2  g_ell[(size_t)Nn * CAP];   // {src*16, __float_as_int(w)} per dst row

// ---------------------------------------------------------------------------
// ELL build: 8 edges per thread, front-batched loads -> 8 independent
// load->atomic->store chains in flight. Stores src PREMULTIPLIED by 16
// (float4-row offset) so gather skips the IMAD. cnt must be zeroed first.
// ---------------------------------------------------------------------------
__global__ __launch_bounds__(256) void ell_fill_kernel(
    const int* __restrict__ src, const int* __restrict__ dst,
    const float* __restrict__ ew, int* __restrict__ cnt,
    int2* __restrict__ ell)
{
    unsigned e0 = blockIdx.x * 256u + threadIdx.x;
    if (e0 >= FO) return;
    int d[8], s[8]; float w[8];
#pragma unroll
    for (int q = 0; q < 8; q++) {
        unsigned e = e0 + q * (unsigned)FO;
        d[q] = __ldg(dst + e);
        s[q] = __ldg(src + e);
        w[q] = __ldg(ew + e);
    }
    int p[8];
#pragma unroll
    for (int q = 0; q < 8; q++)
        p[q] = atomicAdd(&cnt[d[q]], 1);
#pragma unroll
    for (int q = 0; q < 8; q++)
        if (p[q] < CAP)
            ell[(size_t)d[q] * CAP + p[q]] = make_int2(s[q] * 16, __float_as_int(w[q]));
}

// ---------------------------------------------------------------------------
// ELL gather: agg[node] = (1+eps)*h[node] + sum_{edges} w * h[src]
// 16 threads per node, 4 columns (1 float4) each. 4-edge unroll with
// double-buffered index loads; premultiplied src -> address = base + idx + lane.
// (R13-validated optimum: ~40 regs, 58% occ; deeper unrolls regress.)
// ---------------------------------------------------------------------------
__global__ __launch_bounds__(256) void gather_kernel(
    const float4* __restrict__ h4,
    const int* __restrict__ cnt,
    const int2* __restrict__ ell, const float* __restrict__ eps_p,
    float4* __restrict__ agg4)
{
    unsigned t = blockIdx.x * 256u + threadIdx.x;
    unsigned node = t >> 4;
    if (node >= Nn) return;
    const int lane = t & 15;         // column quad: cols [lane*4, lane*4+4)
    const float epsv = 1.0f + __ldg(eps_p);

    float4 a0 = h4[(size_t)node * 16 + lane];
    a0.x *= epsv; a0.y *= epsv; a0.z *= epsv; a0.w *= epsv;

    const float4* hl = h4 + lane;    // lane-offset base; edge addr = hl + idx16

    int num = __ldg(cnt + node);
    if (num > CAP) num = CAP;
    const int2* sw = ell + (size_t)node * CAP;
    int j = 0;
    if (num >= 4) {
        int4 pA = __ldg((const int4*)(sw));
        int4 pB = __ldg((const int4*)(sw + 2));
        for (;;) {
            const int jn = j + 4;
            const bool more = (jn + 4 <= num);
            int4 nA, nB;
            if (more) {
                nA = __ldg((const int4*)(sw + jn));
                nB = __ldg((const int4*)(sw + jn + 2));
            }
            float4 v0 = hl[pA.x];
            float4 v1 = hl[pA.z];
            float4 v2 = hl[pB.x];
            float4 v3 = hl[pB.z];
            float w0 = __int_as_float(pA.y), w1 = __int_as_float(pA.w);
            float w2 = __int_as_float(pB.y), w3 = __int_as_float(pB.w);
            a0.x = fmaf(w0, v0.x, a0.x); a0.y = fmaf(w0, v0.y, a0.y);
            a0.z = fmaf(w0, v0.z, a0.z); a0.w = fmaf(w0, v0.w, a0.w);
            a0.x = fmaf(w1, v1.x, a0.x); a0.y = fmaf(w1, v1.y, a0.y);
            a0.z = fmaf(w1, v1.z, a0.z); a0.w = fmaf(w1, v1.w, a0.w);
            a0.x = fmaf(w2, v2.x, a0.x); a0.y = fmaf(w2, v2.y, a0.y);
            a0.z = fmaf(w2, v2.z, a0.z); a0.w = fmaf(w2, v2.w, a0.w);
            a0.x = fmaf(w3, v3.x, a0.x); a0.y = fmaf(w3, v3.y, a0.y);
            a0.z = fmaf(w3, v3.z, a0.z); a0.w = fmaf(w3, v3.w, a0.w);
            j = jn;
            if (!more) break;
            pA = nA; pB = nB;
        }
    }
    for (; j + 2 <= num; j += 2) {
        int4 pA = __ldg((const int4*)(sw + j));
        float4 v0 = hl[pA.x];
        float4 v1 = hl[pA.z];
        float w0 = __int_as_float(pA.y), w1 = __int_as_float(pA.w);
        a0.x = fmaf(w0, v0.x, a0.x); a0.y = fmaf(w0, v0.y, a0.y);
        a0.z = fmaf(w0, v0.z, a0.z); a0.w = fmaf(w0, v0.w, a0.w);
        a0.x = fmaf(w1, v1.x, a0.x); a0.y = fmaf(w1, v1.y, a0.y);
        a0.z = fmaf(w1, v1.z, a0.z); a0.w = fmaf(w1, v1.w, a0.w);
    }
    if (j < num) {
        int2 e0 = __ldg(sw + j);
        float4 v0 = hl[e0.x];
        float w0 = __int_as_float(e0.y);
        a0.x = fmaf(w0, v0.x, a0.x); a0.y = fmaf(w0, v0.y, a0.y);
        a0.z = fmaf(w0, v0.z, a0.z); a0.w = fmaf(w0, v0.w, a0.w);
    }
    agg4[(size_t)node * 16 + lane] = a0;
}

// ---------------------------------------------------------------------------
// Fused per-layer MLP (z already in 'zin'):
//   t = relu(BN(z@W1 + b1)) ; h' = relu(t@W2 + b2)
//   h_out <- h' (direct STG.128) ; pool[batch[r], layer*128+c] += h'*mask[r]
// Single shared weight buffer (W1 then W2). smem ~34.8KB, launch_bounds(256,5)
// -> 5 CTAs/SM (R11-validated optimum; 6 causes register spills).
// Blocks < 32 also write the previous layer's center rows.
// ---------------------------------------------------------------------------
__global__ __launch_bounds__(256, 5) void fused_mlp(
    const float* __restrict__ zin, const float* __restrict__ h_prev,
    const float* __restrict__ W1, const float* __restrict__ b1,
    const float* __restrict__ gamma, const float* __restrict__ beta,
    const float* __restrict__ bn_mean, const float* __restrict__ bn_var,
    const float* __restrict__ W2, const float* __restrict__ b2,
    float* __restrict__ h_out, const float* __restrict__ mask,
    const int* __restrict__ batch, const int* __restrict__ mapping,
    float* __restrict__ pool, int layer)
{
    extern __shared__ float sm[];
    float* sW = sm;                    // 4096 floats (64x64), W1 then W2
    float* sZ = sm + 4096;             // 64 x ZPAD (z, then t in-place)
    __shared__ float sScale[64], sShift[64], sB1[64], sB2[64];

    const int tid = threadIdx.x;
    const int rowBase = blockIdx.x * 64;

    float4* sWv = (float4*)sW;
    const float4* W1v = (const float4*)W1;
    const float4* W2v = (const float4*)W2;
#pragma unroll
    for (int i = 0; i < 4; i++)
        sWv[tid + i * 256] = W1v[tid + i * 256];
    if (tid < 64) {
        float sc = __ldg(gamma + tid) * rsqrtf(__ldg(bn_var + tid) + 1e-5f);
        sScale[tid] = sc;
        sShift[tid] = __ldg(beta + tid) - __ldg(bn_mean + tid) * sc;
        sB1[tid] = __ldg(b1 + tid);
        sB2[tid] = __ldg(b2 + tid);
    }

    // Previous layer's center gather (h_prev is the completed previous output)
    if (layer > 0 && blockIdx.x < 32) {
        int t2 = blockIdx.x * 256 + tid;   // 0..8191 = 512*16
        int gg = t2 >> 4, cc = t2 & 15;
        ((float4*)pool)[gg * (POOLW / 4) + (layer - 1) * 32 + 16 + cc] =
            ((const float4*)h_prev)[(size_t)__ldg(mapping + gg) * 16 + cc];
    }

    // Load z tile (row-major, stride ZPAD)
    const float4* z4 = (const float4*)zin;
#pragma unroll
    for (int i = 0; i < 4; i++) {
        int t = tid + i * 256;
        int r = t >> 4, c4 = t & 15;
        int gr = rowBase + r;
        float4 z = (gr < Nn) ? z4[(size_t)gr * 16 + c4]
                             : make_float4(0.f, 0.f, 0.f, 0.f);
        *(float4*)&sZ[r * ZPAD + c4 * 4] = z;
    }
    __syncthreads();

    const int tx = tid & 15, ty = tid >> 4;
    const int c0 = tx * 4, r0 = ty * 4;

    // ---- GEMM1: acc = z @ W1 (FFMA2; A via LDS.128 per 4k, B per-kk LDS.128)
    unsigned long long acc01[4] = {}, acc23[4] = {};
    {
        const float4* sZr = (const float4*)sZ;
        const ulonglong2* sWq = (const ulonglong2*)sW;
#pragma unroll
        for (int k4 = 0; k4 < 16; k4++) {
            float4 av[4];
#pragma unroll
            for (int i = 0; i < 4; i++)
                av[i] = sZr[(r0 + i) * (ZPAD / 4) + k4];
#pragma unroll
            for (int kk = 0; kk < 4; kk++) {
                ulonglong2 b = sWq[(k4 * 4 + kk) * 16 + tx];
#pragma unroll
                for (int i = 0; i < 4; i++) {
                    float a = (kk == 0) ? av[i].x : (kk == 1) ? av[i].y
                            : (kk == 2) ? av[i].z : av[i].w;
                    unsigned au = __float_as_uint(a);
                    unsigned long long aa;
                    asm("mov.b64 %0, {%1, %1};" : "=l"(aa) : "r"(au));
                    asm("fma.rn.f32x2 %0, %1, %2, %0;" : "+l"(acc01[i]) : "l"(aa), "l"(b.x));
                    asm("fma.rn.f32x2 %0, %1, %2, %0;" : "+l"(acc23[i]) : "l"(aa), "l"(b.y));
                }
            }
        }
    }
    __syncthreads();   // all GEMM1 reads of sZ and sW complete

    // Reload weight buffer with W2 (L2-broadcast-hot across CTAs)
#pragma unroll
    for (int i = 0; i < 4; i++)
        sWv[tid + i * 256] = W2v[tid + i * 256];

    // +b1, BN(eval), ReLU -> back into sZ (t tile, same ZPAD layout)
    {
        float4 bb1 = *(const float4*)&sB1[c0];
        float4 scv = *(const float4*)&sScale[c0];
        float4 shv = *(const float4*)&sShift[c0];
#pragma unroll
        for (int i = 0; i < 4; i++) {
            unsigned u0, u1, u2, u3;
            asm("mov.b64 {%0, %1}, %2;" : "=r"(u0), "=r"(u1) : "l"(acc01[i]));
            asm("mov.b64 {%0, %1}, %2;" : "=r"(u2), "=r"(u3) : "l"(acc23[i]));
            float4 v;
            v.x = fmaxf(fmaf(__uint_as_float(u0) + bb1.x, scv.x, shv.x), 0.f);
            v.y = fmaxf(fmaf(__uint_as_float(u1) + bb1.y, scv.y, shv.y), 0.f);
            v.z = fmaxf(fmaf(__uint_as_float(u2) + bb1.z, scv.z, shv.z), 0.f);
            v.w = fmaxf(fmaf(__uint_as_float(u3) + bb1.w, scv.w, shv.w), 0.f);
            *(float4*)&sZ[(r0 + i) * ZPAD + c0] = v;
        }
    }
    __syncthreads();   // t and W2 visible

    // ---- GEMM2: acc2 = t @ W2
    unsigned long long bcc01[4] = {}, bcc23[4] = {};
    {
        const float4* sTr = (const float4*)sZ;
        const ulonglong2* sWq = (const ulonglong2*)sW;
#pragma unroll
        for (int k4 = 0; k4 < 16; k4++) {
            float4 av[4];
#pragma unroll
            for (int i = 0; i < 4; i++)
                av[i] = sTr[(r0 + i) * (ZPAD / 4) + k4];
#pragma unroll
            for (int kk = 0; kk < 4; kk++) {
                ulonglong2 b = sWq[(k4 * 4 + kk) * 16 + tx];
#pragma unroll
                for (int i = 0; i < 4; i++) {
                    float a = (kk == 0) ? av[i].x : (kk == 1) ? av[i].y
                            : (kk == 2) ? av[i].z : av[i].w;
                    unsigned au = __float_as_uint(a);
                    unsigned long long aa;
                    asm("mov.b64 %0, {%1, %1};" : "=l"(aa) : "r"(au));
                    asm("fma.rn.f32x2 %0, %1, %2, %0;" : "+l"(bcc01[i]) : "l"(aa), "l"(b.x));
                    asm("fma.rn.f32x2 %0, %1, %2, %0;" : "+l"(bcc23[i]) : "l"(aa), "l"(b.y));
                }
            }
        }
    }

    // +b2, ReLU -> DIRECT global write (STG.128, coalesced across tx) + pool red
    {
        float4 bb2 = *(const float4*)&sB2[c0];
        float4* ho4 = (float4*)h_out;
#pragma unroll
        for (int i = 0; i < 4; i++) {
            int gr = rowBase + r0 + i;
            if (gr >= Nn) continue;
            unsigned u0, u1, u2, u3;
            asm("mov.b64 {%0, %1}, %2;" : "=r"(u0), "=r"(u1) : "l"(bcc01[i]));
            asm("mov.b64 {%0, %1}, %2;" : "=r"(u2), "=r"(u3) : "l"(bcc23[i]));
            float4 v;
            v.x = fmaxf(__uint_as_float(u0) + bb2.x, 0.f);
            v.y = fmaxf(__uint_as_float(u1) + bb2.y, 0.f);
            v.z = fmaxf(__uint_as_float(u2) + bb2.z, 0.f);
            v.w = fmaxf(__uint_as_float(u3) + bb2.w, 0.f);
            ho4[(size_t)gr * 16 + tx] = v;
            float w = __ldg(mask + gr);
            if (w != 0.f) {
                float* addr = pool + (size_t)__ldg(batch + gr) * POOLW + layer * 128 + c0;
                float4 p = make_float4(v.x * w, v.y * w, v.z * w, v.w * w);
                asm volatile("red.global.add.v4.f32 [%0], {%1, %2, %3, %4};"
                             :: "l"(addr), "f"(p.x), "f"(p.y), "f"(p.z), "f"(p.w)
                             : "memory");
            }
        }
    }
}

// ---------------------------------------------------------------------------
// Final projection with fused layer-2 center gather:
// out[g,s] = sum_{k<320} pool[g,k]*lw[k,s] + sum_{k<64} h[map[g],k]*lw[320+k,s] + lb[s]
// ---------------------------------------------------------------------------
__global__ __launch_bounds__(128) void final_kernel(
    const float* __restrict__ pool, const float* __restrict__ hfin,
    const int* __restrict__ mapping,
    const float* __restrict__ lw, const float* __restrict__ lb,
    float* __restrict__ out)
{
    int g = blockIdx.x * 4 + (threadIdx.x >> 5);
    int s = threadIdx.x & 31;
    const float* pr = pool + (size_t)g * POOLW;
    const float* hc = hfin + (size_t)__ldg(mapping + g) * Dd;
    float acc = __ldg(lb + s);
#pragma unroll 4
    for (int k = 0; k < 320; k++)
        acc = fmaf(__ldg(pr + k), __ldg(lw + k * Ss + s), acc);
#pragma unroll 4
    for (int k = 0; k < Dd; k++)
        acc = fmaf(__ldg(hc + k), __ldg(lw + (320 + k) * Ss + s), acc);
    out[g * Ss + s] = acc;
}

extern "C" void kernel_launch(void* const* d_in, const int* in_sizes, int n_in,
                              void* d_out, int out_size)
{
    const float* x       = (const float*)d_in[0];
    const float* ew      = (const float*)d_in[1];
    const float* mask    = (const float*)d_in[2];
    const float* W1      = (const float*)d_in[3];
    const float* b1      = (const float*)d_in[4];
    const float* gamma   = (const float*)d_in[5];
    const float* beta    = (const float*)d_in[6];
    const float* bn_mean = (const float*)d_in[7];
    const float* bn_var  = (const float*)d_in[8];
    const float* W2      = (const float*)d_in[9];
    const float* b2      = (const float*)d_in[10];
    const float* eps     = (const float*)d_in[11];
    const float* lin_w   = (const float*)d_in[12];
    const float* lin_b   = (const float*)d_in[13];
    const int* edge_index = (const int*)d_in[14];
    const int* batch      = (const int*)d_in[15];
    const int* mapping    = (const int*)d_in[16];
    float* out = (float*)d_out;

    float *hbuf = nullptr, *hbuf2 = nullptr, *aggbuf = nullptr, *poolbuf = nullptr;
    int *cntb = nullptr;
    int2 *ellb = nullptr;
    (void)cudaGetSymbolAddress((void**)&hbuf, g_h);
    (void)cudaGetSymbolAddress((void**)&hbuf2, g_h2);
    (void)cudaGetSymbolAddress((void**)&aggbuf, g_agg);
    (void)cudaGetSymbolAddress((void**)&poolbuf, g_pool);
    (void)cudaGetSymbolAddress((void**)&cntb, g_cnt);
    (void)cudaGetSymbolAddress((void**)&ellb, g_ell);

    const int SMEM_BYTES = (4096 + 64*ZPAD) * (int)sizeof(float);  // ~33.8KB
    (void)cudaFuncSetAttribute(fused_mlp, cudaFuncAttributeMaxDynamicSharedMemorySize, SMEM_BYTES);

    cudaMemsetAsync(cntb, 0, Nn * sizeof(int));
    cudaMemsetAsync(poolbuf, 0, (size_t)Gg * POOLW * sizeof(float));

    const int* srcp = edge_index;
    const int* dstp = edge_index + Ee;

    ell_fill_kernel<<<(FO + 255) / 256, 256>>>(srcp, dstp, ew, cntb, ellb);

    const float* hin = x;
    float* houts[3] = {hbuf, hbuf2, hbuf};
    for (int l = 0; l < Ll; l++) {
        gather_kernel<<<(Nn * 16 + 255) / 256, 256>>>(
            (const float4*)hin, cntb, ellb, eps + l, (float4*)aggbuf);
        fused_mlp<<<(Nn + 63) / 64, 256, SMEM_BYTES>>>(
            aggbuf, hin,
            W1 + l * Dd * Dd, b1 + l * Dd,
            gamma + l * Dd, beta + l * Dd, bn_mean + l * Dd, bn_var + l * Dd,
            W2 + l * Dd * Dd, b2 + l * Dd,
            houts[l], mask, batch, mapping, poolbuf, l);
        hin = houts[l];
    }
    final_kernel<<<Gg / 4, 128>>>(poolbuf, hbuf, mapping, lin_w, lin_b, out);
}

// round 17
// speedup vs baseline: 1.4605x; 1.0123x over previous
#include <cuda_runtime.h>
#include <cuda_bf16.h>
#include <cstdint>

#define Nn 50000
#define Ee 800000
#define Dd 64
#define Ll 3
#define Gg 512
#define Ss 32
#define POOLW (2*Dd*Ll)   // 384
#define ZPAD 68           // sZ row stride in floats (17 float4s, 16B aligned)
#define CAP 64            // ELL row capacity (deg ~ Poisson(16); P(>=64) ~ 2e-18)
#define FO (Ee/8)         // 100000 edges per fill-octet

// Scratch (no allocations allowed). Zero-initialized at module load; kernels
// re-zero cnt/pool at the end of each replay (self-cleaning, graph-friendly).
__device__ float g_h[Nn * Dd];
__device__ float g_h2[Nn * Dd];
__device__ float g_agg[Nn * Dd];
__device__ float g_pool[Gg * POOLW];
__device__ int   g_cnt[Nn];
__device__ int2  g_ell[(size_t)Nn * CAP];   // {src*16, __float_as_int(w)} per dst row

// ---------------------------------------------------------------------------
// ELL build: 8 edges per thread, front-batched loads -> 8 independent
// load->atomic->store chains in flight. Stores src PREMULTIPLIED by 16
// (float4-row offset) so gather skips the IMAD. cnt is zero on entry
// (zeroed by the previous replay's layer-2 fused_mlp, or static init).
// ---------------------------------------------------------------------------
__global__ __launch_bounds__(256) void ell_fill_kernel(
    const int* __restrict__ src, const int* __restrict__ dst,
    const float* __restrict__ ew, int* __restrict__ cnt,
    int2* __restrict__ ell)
{
    unsigned e0 = blockIdx.x * 256u + threadIdx.x;
    if (e0 >= FO) return;
    int d[8], s[8]; float w[8];
#pragma unroll
    for (int q = 0; q < 8; q++) {
        unsigned e = e0 + q * (unsigned)FO;
        d[q] = __ldg(dst + e);
        s[q] = __ldg(src + e);
        w[q] = __ldg(ew + e);
    }
    int p[8];
#pragma unroll
    for (int q = 0; q < 8; q++)
        p[q] = atomicAdd(&cnt[d[q]], 1);
#pragma unroll
    for (int q = 0; q < 8; q++)
        if (p[q] < CAP)
            ell[(size_t)d[q] * CAP + p[q]] = make_int2(s[q] * 16, __float_as_int(w[q]));
}

// ---------------------------------------------------------------------------
// ELL gather: agg[node] = (1+eps)*h[node] + sum_{edges} w * h[src]
// 16 threads per node, 4 columns (1 float4) each. 4-edge unroll with
// double-buffered index loads; premultiplied src -> address = base + idx + lane.
// (R13-validated optimum: ~40 regs, 58% occ; deeper unrolls regress.)
// ---------------------------------------------------------------------------
__global__ __launch_bounds__(256) void gather_kernel(
    const float4* __restrict__ h4,
    const int* __restrict__ cnt,
    const int2* __restrict__ ell, const float* __restrict__ eps_p,
    float4* __restrict__ agg4)
{
    unsigned t = blockIdx.x * 256u + threadIdx.x;
    unsigned node = t >> 4;
    if (node >= Nn) return;
    const int lane = t & 15;         // column quad: cols [lane*4, lane*4+4)
    const float epsv = 1.0f + __ldg(eps_p);

    float4 a0 = h4[(size_t)node * 16 + lane];
    a0.x *= epsv; a0.y *= epsv; a0.z *= epsv; a0.w *= epsv;

    const float4* hl = h4 + lane;    // lane-offset base; edge addr = hl + idx16

    int num = __ldg(cnt + node);
    if (num > CAP) num = CAP;
    const int2* sw = ell + (size_t)node * CAP;
    int j = 0;
    if (num >= 4) {
        int4 pA = __ldg((const int4*)(sw));
        int4 pB = __ldg((const int4*)(sw + 2));
        for (;;) {
            const int jn = j + 4;
            const bool more = (jn + 4 <= num);
            int4 nA, nB;
            if (more) {
                nA = __ldg((const int4*)(sw + jn));
                nB = __ldg((const int4*)(sw + jn + 2));
            }
            float4 v0 = hl[pA.x];
            float4 v1 = hl[pA.z];
            float4 v2 = hl[pB.x];
            float4 v3 = hl[pB.z];
            float w0 = __int_as_float(pA.y), w1 = __int_as_float(pA.w);
            float w2 = __int_as_float(pB.y), w3 = __int_as_float(pB.w);
            a0.x = fmaf(w0, v0.x, a0.x); a0.y = fmaf(w0, v0.y, a0.y);
            a0.z = fmaf(w0, v0.z, a0.z); a0.w = fmaf(w0, v0.w, a0.w);
            a0.x = fmaf(w1, v1.x, a0.x); a0.y = fmaf(w1, v1.y, a0.y);
            a0.z = fmaf(w1, v1.z, a0.z); a0.w = fmaf(w1, v1.w, a0.w);
            a0.x = fmaf(w2, v2.x, a0.x); a0.y = fmaf(w2, v2.y, a0.y);
            a0.z = fmaf(w2, v2.z, a0.z); a0.w = fmaf(w2, v2.w, a0.w);
            a0.x = fmaf(w3, v3.x, a0.x); a0.y = fmaf(w3, v3.y, a0.y);
            a0.z = fmaf(w3, v3.z, a0.z); a0.w = fmaf(w3, v3.w, a0.w);
            j = jn;
            if (!more) break;
            pA = nA; pB = nB;
        }
    }
    for (; j + 2 <= num; j += 2) {
        int4 pA = __ldg((const int4*)(sw + j));
        float4 v0 = hl[pA.x];
        float4 v1 = hl[pA.z];
        float w0 = __int_as_float(pA.y), w1 = __int_as_float(pA.w);
        a0.x = fmaf(w0, v0.x, a0.x); a0.y = fmaf(w0, v0.y, a0.y);
        a0.z = fmaf(w0, v0.z, a0.z); a0.w = fmaf(w0, v0.w, a0.w);
        a0.x = fmaf(w1, v1.x, a0.x); a0.y = fmaf(w1, v1.y, a0.y);
        a0.z = fmaf(w1, v1.z, a0.z); a0.w = fmaf(w1, v1.w, a0.w);
    }
    if (j < num) {
        int2 e0 = __ldg(sw + j);
        float4 v0 = hl[e0.x];
        float w0 = __int_as_float(e0.y);
        a0.x = fmaf(w0, v0.x, a0.x); a0.y = fmaf(w0, v0.y, a0.y);
        a0.z = fmaf(w0, v0.z, a0.z); a0.w = fmaf(w0, v0.w, a0.w);
    }
    agg4[(size_t)node * 16 + lane] = a0;
}

// ---------------------------------------------------------------------------
// Fused per-layer MLP (z already in 'zin'):
//   t = relu(BN(z@W1 + b1)) ; h' = relu(t@W2 + b2)
//   h_out <- h' (direct STG.128) ; pool[batch[r], layer*128+c] += h'*mask[r]
// Single shared weight buffer (W1 then W2). smem ~34.8KB, launch_bounds(256,5)
// -> 5 CTAs/SM (R11-validated optimum; 6 causes register spills).
// Blocks < 32 also write the previous layer's center rows.
// Layer 2 additionally re-zeroes cnt[] for the next graph replay (runs after
// the last gather has read cnt; mlp itself never reads cnt -> race-free).
// ---------------------------------------------------------------------------
__global__ __launch_bounds__(256, 5) void fused_mlp(
    const float* __restrict__ zin, const float* __restrict__ h_prev,
    const float* __restrict__ W1, const float* __restrict__ b1,
    const float* __restrict__ gamma, const float* __restrict__ beta,
    const float* __restrict__ bn_mean, const float* __restrict__ bn_var,
    const float* __restrict__ W2, const float* __restrict__ b2,
    float* __restrict__ h_out, const float* __restrict__ mask,
    const int* __restrict__ batch, const int* __restrict__ mapping,
    float* __restrict__ pool, int layer, int* __restrict__ cnt_zero)
{
    extern __shared__ float sm[];
    float* sW = sm;                    // 4096 floats (64x64), W1 then W2
    float* sZ = sm + 4096;             // 64 x ZPAD (z, then t in-place)
    __shared__ float sScale[64], sShift[64], sB1[64], sB2[64];

    const int tid = threadIdx.x;
    const int rowBase = blockIdx.x * 64;

    // Self-clean: re-zero cnt for the next replay (layer 2 only)
    if (cnt_zero) {
        int i = blockIdx.x * 256 + tid;
        if (i < Nn) cnt_zero[i] = 0;
    }

    float4* sWv = (float4*)sW;
    const float4* W1v = (const float4*)W1;
    const float4* W2v = (const float4*)W2;
#pragma unroll
    for (int i = 0; i < 4; i++)
        sWv[tid + i * 256] = W1v[tid + i * 256];
    if (tid < 64) {
        float sc = __ldg(gamma + tid) * rsqrtf(__ldg(bn_var + tid) + 1e-5f);
        sScale[tid] = sc;
        sShift[tid] = __ldg(beta + tid) - __ldg(bn_mean + tid) * sc;
        sB1[tid] = __ldg(b1 + tid);
        sB2[tid] = __ldg(b2 + tid);
    }

    // Previous layer's center gather (h_prev is the completed previous output)
    if (layer > 0 && blockIdx.x < 32) {
        int t2 = blockIdx.x * 256 + tid;   // 0..8191 = 512*16
        int gg = t2 >> 4, cc = t2 & 15;
        ((float4*)pool)[gg * (POOLW / 4) + (layer - 1) * 32 + 16 + cc] =
            ((const float4*)h_prev)[(size_t)__ldg(mapping + gg) * 16 + cc];
    }

    // Load z tile (row-major, stride ZPAD)
    const float4* z4 = (const float4*)zin;
#pragma unroll
    for (int i = 0; i < 4; i++) {
        int t = tid + i * 256;
        int r = t >> 4, c4 = t & 15;
        int gr = rowBase + r;
        float4 z = (gr < Nn) ? z4[(size_t)gr * 16 + c4]
                             : make_float4(0.f, 0.f, 0.f, 0.f);
        *(float4*)&sZ[r * ZPAD + c4 * 4] = z;
    }
    __syncthreads();

    const int tx = tid & 15, ty = tid >> 4;
    const int c0 = tx * 4, r0 = ty * 4;

    // ---- GEMM1: acc = z @ W1 (FFMA2; A via LDS.128 per 4k, B per-kk LDS.128)
    unsigned long long acc01[4] = {}, acc23[4] = {};
    {
        const float4* sZr = (const float4*)sZ;
        const ulonglong2* sWq = (const ulonglong2*)sW;
#pragma unroll
        for (int k4 = 0; k4 < 16; k4++) {
            float4 av[4];
#pragma unroll
            for (int i = 0; i < 4; i++)
                av[i] = sZr[(r0 + i) * (ZPAD / 4) + k4];
#pragma unroll
            for (int kk = 0; kk < 4; kk++) {
                ulonglong2 b = sWq[(k4 * 4 + kk) * 16 + tx];
#pragma unroll
                for (int i = 0; i < 4; i++) {
                    float a = (kk == 0) ? av[i].x : (kk == 1) ? av[i].y
                            : (kk == 2) ? av[i].z : av[i].w;
                    unsigned au = __float_as_uint(a);
                    unsigned long long aa;
                    asm("mov.b64 %0, {%1, %1};" : "=l"(aa) : "r"(au));
                    asm("fma.rn.f32x2 %0, %1, %2, %0;" : "+l"(acc01[i]) : "l"(aa), "l"(b.x));
                    asm("fma.rn.f32x2 %0, %1, %2, %0;" : "+l"(acc23[i]) : "l"(aa), "l"(b.y));
                }
            }
        }
    }
    __syncthreads();   // all GEMM1 reads of sZ and sW complete

    // Reload weight buffer with W2 (L2-broadcast-hot across CTAs)
#pragma unroll
    for (int i = 0; i < 4; i++)
        sWv[tid + i * 256] = W2v[tid + i * 256];

    // +b1, BN(eval), ReLU -> back into sZ (t tile, same ZPAD layout)
    {
        float4 bb1 = *(const float4*)&sB1[c0];
        float4 scv = *(const float4*)&sScale[c0];
        float4 shv = *(const float4*)&sShift[c0];
#pragma unroll
        for (int i = 0; i < 4; i++) {
            unsigned u0, u1, u2, u3;
            asm("mov.b64 {%0, %1}, %2;" : "=r"(u0), "=r"(u1) : "l"(acc01[i]));
            asm("mov.b64 {%0, %1}, %2;" : "=r"(u2), "=r"(u3) : "l"(acc23[i]));
            float4 v;
            v.x = fmaxf(fmaf(__uint_as_float(u0) + bb1.x, scv.x, shv.x), 0.f);
            v.y = fmaxf(fmaf(__uint_as_float(u1) + bb1.y, scv.y, shv.y), 0.f);
            v.z = fmaxf(fmaf(__uint_as_float(u2) + bb1.z, scv.z, shv.z), 0.f);
            v.w = fmaxf(fmaf(__uint_as_float(u3) + bb1.w, scv.w, shv.w), 0.f);
            *(float4*)&sZ[(r0 + i) * ZPAD + c0] = v;
        }
    }
    __syncthreads();   // t and W2 visible

    // ---- GEMM2: acc2 = t @ W2
    unsigned long long bcc01[4] = {}, bcc23[4] = {};
    {
        const float4* sTr = (const float4*)sZ;
        const ulonglong2* sWq = (const ulonglong2*)sW;
#pragma unroll
        for (int k4 = 0; k4 < 16; k4++) {
            float4 av[4];
#pragma unroll
            for (int i = 0; i < 4; i++)
                av[i] = sTr[(r0 + i) * (ZPAD / 4) + k4];
#pragma unroll
            for (int kk = 0; kk < 4; kk++) {
                ulonglong2 b = sWq[(k4 * 4 + kk) * 16 + tx];
#pragma unroll
                for (int i = 0; i < 4; i++) {
                    float a = (kk == 0) ? av[i].x : (kk == 1) ? av[i].y
                            : (kk == 2) ? av[i].z : av[i].w;
                    unsigned au = __float_as_uint(a);
                    unsigned long long aa;
                    asm("mov.b64 %0, {%1, %1};" : "=l"(aa) : "r"(au));
                    asm("fma.rn.f32x2 %0, %1, %2, %0;" : "+l"(bcc01[i]) : "l"(aa), "l"(b.x));
                    asm("fma.rn.f32x2 %0, %1, %2, %0;" : "+l"(bcc23[i]) : "l"(aa), "l"(b.y));
                }
            }
        }
    }

    // +b2, ReLU -> DIRECT global write (STG.128, coalesced across tx) + pool red
    {
        float4 bb2 = *(const float4*)&sB2[c0];
        float4* ho4 = (float4*)h_out;
#pragma unroll
        for (int i = 0; i < 4; i++) {
            int gr = rowBase + r0 + i;
            if (gr >= Nn) continue;
            unsigned u0, u1, u2, u3;
            asm("mov.b64 {%0, %1}, %2;" : "=r"(u0), "=r"(u1) : "l"(bcc01[i]));
            asm("mov.b64 {%0, %1}, %2;" : "=r"(u2), "=r"(u3) : "l"(bcc23[i]));
            float4 v;
            v.x = fmaxf(__uint_as_float(u0) + bb2.x, 0.f);
            v.y = fmaxf(__uint_as_float(u1) + bb2.y, 0.f);
            v.z = fmaxf(__uint_as_float(u2) + bb2.z, 0.f);
            v.w = fmaxf(__uint_as_float(u3) + bb2.w, 0.f);
            ho4[(size_t)gr * 16 + tx] = v;
            float w = __ldg(mask + gr);
            if (w != 0.f) {
                float* addr = pool + (size_t)__ldg(batch + gr) * POOLW + layer * 128 + c0;
                float4 p = make_float4(v.x * w, v.y * w, v.z * w, v.w * w);
                asm volatile("red.global.add.v4.f32 [%0], {%1, %2, %3, %4};"
                             :: "l"(addr), "f"(p.x), "f"(p.y), "f"(p.z), "f"(p.w)
                             : "memory");
            }
        }
    }
}

// ---------------------------------------------------------------------------
// Final projection with fused layer-2 center gather:
// out[g,s] = sum_{k<320} pool[g,k]*lw[k,s] + sum_{k<64} h[map[g],k]*lw[320+k,s] + lb[s]
// After computing, each warp re-zeroes its row's add-pool regions for the
// next replay (center regions are fully overwritten each replay).
// ---------------------------------------------------------------------------
__global__ __launch_bounds__(128) void final_kernel(
    float* __restrict__ pool, const float* __restrict__ hfin,
    const int* __restrict__ mapping,
    const float* __restrict__ lw, const float* __restrict__ lb,
    float* __restrict__ out)
{
    int g = blockIdx.x * 4 + (threadIdx.x >> 5);
    int s = threadIdx.x & 31;
    float* pr = pool + (size_t)g * POOLW;
    const float* hc = hfin + (size_t)__ldg(mapping + g) * Dd;
    float acc = __ldg(lb + s);
#pragma unroll 4
    for (int k = 0; k < 320; k++)
        acc = fmaf(pr[k], __ldg(lw + k * Ss + s), acc);
#pragma unroll 4
    for (int k = 0; k < Dd; k++)
        acc = fmaf(__ldg(hc + k), __ldg(lw + (320 + k) * Ss + s), acc);
    out[g * Ss + s] = acc;

    // Self-clean: zero this row's add-pool regions (layer*128 + [0,64)).
    // All 32 lanes of this warp have finished reading row g above.
    __syncwarp();
#pragma unroll
    for (int l = 0; l < Ll; l++) {
        pr[l * 128 + s] = 0.f;
        pr[l * 128 + 32 + s] = 0.f;
    }
}

extern "C" void kernel_launch(void* const* d_in, const int* in_sizes, int n_in,
                              void* d_out, int out_size)
{
    const float* x       = (const float*)d_in[0];
    const float* ew      = (const float*)d_in[1];
    const float* mask    = (const float*)d_in[2];
    const float* W1      = (const float*)d_in[3];
    const float* b1      = (const float*)d_in[4];
    const float* gamma   = (const float*)d_in[5];
    const float* beta    = (const float*)d_in[6];
    const float* bn_mean = (const float*)d_in[7];
    const float* bn_var  = (const float*)d_in[8];
    const float* W2      = (const float*)d_in[9];
    const float* b2      = (const float*)d_in[10];
    const float* eps     = (const float*)d_in[11];
    const float* lin_w   = (const float*)d_in[12];
    const float* lin_b   = (const float*)d_in[13];
    const int* edge_index = (const int*)d_in[14];
    const int* batch      = (const int*)d_in[15];
    const int* mapping    = (const int*)d_in[16];
    float* out = (float*)d_out;

    float *hbuf = nullptr, *hbuf2 = nullptr, *aggbuf = nullptr, *poolbuf = nullptr;
    int *cntb = nullptr;
    int2 *ellb = nullptr;
    (void)cudaGetSymbolAddress((void**)&hbuf, g_h);
    (void)cudaGetSymbolAddress((void**)&hbuf2, g_h2);
    (void)cudaGetSymbolAddress((void**)&aggbuf, g_agg);
    (void)cudaGetSymbolAddress((void**)&poolbuf, g_pool);
    (void)cudaGetSymbolAddress((void**)&cntb, g_cnt);
    (void)cudaGetSymbolAddress((void**)&ellb, g_ell);

    const int SMEM_BYTES = (4096 + 64*ZPAD) * (int)sizeof(float);  // ~33.8KB
    (void)cudaFuncSetAttribute(fused_mlp, cudaFuncAttributeMaxDynamicSharedMemorySize, SMEM_BYTES);

    const int* srcp = edge_index;
    const int* dstp = edge_index + Ee;

    ell_fill_kernel<<<(FO + 255) / 256, 256>>>(srcp, dstp, ew, cntb, ellb);

    const float* hin = x;
    float* houts[3] = {hbuf, hbuf2, hbuf};
    for (int l = 0; l < Ll; l++) {
        gather_kernel<<<(Nn * 16 + 255) / 256, 256>>>(
            (const float4*)hin, cntb, ellb, eps + l, (float4*)aggbuf);
        fused_mlp<<<(Nn + 63) / 64, 256, SMEM_BYTES>>>(
            aggbuf, hin,
            W1 + l * Dd * Dd, b1 + l * Dd,
            gamma + l * Dd, beta + l * Dd, bn_mean + l * Dd, bn_var + l * Dd,
            W2 + l * Dd * Dd, b2 + l * Dd,
            houts[l], mask, batch, mapping, poolbuf, l,
            (l == Ll - 1) ? cntb : nullptr);
        hin = houts[l];
    }
    final_kernel<<<Gg / 4, 128>>>(poolbuf, hbuf, mapping, lin_w, lin_b, out);
}